// round 5
// baseline (speedup 1.0000x reference)
#include <cuda_runtime.h>
#include <cuda_bf16.h>
#include <cstdint>

#define NUM_NODES 100000
#define NUM_EDGES 50000
#define NUM_CONN  800000
#define IN_DIM    256
#define HIDDEN    128
#define OUT_DIM   17
#define LN_EPS    1e-5f

// ---------------- scratch (static device globals; no allocation) ----------------
__device__ int   g_counts[NUM_EDGES];
__device__ int   g_offsets[NUM_EDGES + 1];
__device__ int   g_cursor[NUM_EDGES];
__device__ int   g_csr[NUM_CONN];
__device__ __align__(16) float g_edge_feat[(size_t)NUM_EDGES * IN_DIM];

// ---------------- packed f32x2 helpers ----------------
__device__ __forceinline__ void fma_f32x2(unsigned long long& d,
                                          unsigned long long a,
                                          unsigned long long b) {
    asm("fma.rn.f32x2 %0, %1, %2, %0;" : "+l"(d) : "l"(a), "l"(b));
}
__device__ __forceinline__ unsigned long long pack_f32x2(float lo, float hi) {
    unsigned long long r;
    asm("mov.b64 %0, {%1, %2};" : "=l"(r) : "f"(lo), "f"(hi));
    return r;
}
__device__ __forceinline__ float2 unpack_f32x2(unsigned long long v) {
    float2 r;
    asm("mov.b64 {%0, %1}, %2;" : "=f"(r.x), "=f"(r.y) : "l"(v));
    return r;
}
__device__ __forceinline__ void cp_async16(void* smem_dst, const void* gsrc) {
    unsigned s = (unsigned)__cvta_generic_to_shared(smem_dst);
    asm volatile("cp.async.cg.shared.global [%0], [%1], 16;" :: "r"(s), "l"(gsrc));
}
__device__ __forceinline__ void cp_async_commit() {
    asm volatile("cp.async.commit_group;");
}
template <int N>
__device__ __forceinline__ void cp_async_wait() {
    asm volatile("cp.async.wait_group %0;" :: "n"(N));
}

// ---------------- K0: zero counts ----------------
__global__ void zero_counts_kernel() {
    int i = blockIdx.x * blockDim.x + threadIdx.x;
    if (i < NUM_EDGES) g_counts[i] = 0;
}

// ---------------- K1: histogram of edge ids (hyperedge_index is int32) ----------------
__global__ void count_kernel(const int* __restrict__ he) {
    int c = blockIdx.x * blockDim.x + threadIdx.x;
    if (c < NUM_CONN) {
        int e = he[NUM_CONN + c];
        if ((unsigned)e < NUM_EDGES) atomicAdd(&g_counts[e], 1);
    }
}

// ---------------- K2: exclusive scan, smem-staged, coalesced ----------------
__global__ void __launch_bounds__(1024) scan_kernel() {
    extern __shared__ int sc[];               // NUM_EDGES ints = 200000 B
    const int PER = 49;
    __shared__ int wsum[32];
    int tid = threadIdx.x, lane = tid & 31, wid = tid >> 5;

    for (int i = tid; i < NUM_EDGES; i += 1024) sc[i] = g_counts[i];
    __syncthreads();

    int base = tid * PER;
    int s = 0;
    #pragma unroll
    for (int i = 0; i < PER; i++) {
        int idx = base + i;
        if (idx < NUM_EDGES) s += sc[idx];
    }
    int x = s;
    #pragma unroll
    for (int off = 1; off < 32; off <<= 1) {
        int t = __shfl_up_sync(0xffffffffu, x, off);
        if (lane >= off) x += t;
    }
    if (lane == 31) wsum[wid] = x;
    __syncthreads();
    if (wid == 0) {
        int t = wsum[lane];
        int y = t;
        #pragma unroll
        for (int off = 1; off < 32; off <<= 1) {
            int u = __shfl_up_sync(0xffffffffu, y, off);
            if (lane >= off) y += u;
        }
        wsum[lane] = y - t;
    }
    __syncthreads();
    int run = (x - s) + wsum[wid];
    #pragma unroll
    for (int i = 0; i < PER; i++) {
        int idx = base + i;
        if (idx < NUM_EDGES) {
            int c = sc[idx];
            sc[idx] = run;
            run += c;
        }
    }
    __syncthreads();
    for (int i = tid; i < NUM_EDGES; i += 1024) {
        int v = sc[i];
        g_offsets[i] = v;
        g_cursor[i]  = v;
    }
    if (tid == 1023) g_offsets[NUM_EDGES] = run;
}

// ---------------- K3: fill CSR ----------------
__global__ void fill_kernel(const int* __restrict__ he) {
    int c = blockIdx.x * blockDim.x + threadIdx.x;
    if (c < NUM_CONN) {
        int e = he[NUM_CONN + c];
        if ((unsigned)e < NUM_EDGES) {
            int pos = atomicAdd(&g_cursor[e], 1);
            int n = he[c];
            g_csr[pos] = ((unsigned)n < NUM_NODES) ? n : 0;
        }
    }
}

// ---------------- K4: warp-per-edge gather + mean (2-way unrolled) ----------------
__global__ void aggregate_kernel(const float* __restrict__ nf) {
    int gw   = (blockIdx.x * blockDim.x + threadIdx.x) >> 5;
    int lane = threadIdx.x & 31;
    if (gw >= NUM_EDGES) return;
    int beg = g_offsets[gw];
    int end = g_offsets[gw + 1];
    float4 a0 = make_float4(0.f, 0.f, 0.f, 0.f);
    float4 a1 = make_float4(0.f, 0.f, 0.f, 0.f);
    int i = beg;
    for (; i + 2 <= end; i += 2) {
        int n0 = g_csr[i];
        int n1 = g_csr[i + 1];
        const float4* r0 = (const float4*)(nf + (size_t)n0 * IN_DIM);
        const float4* r1 = (const float4*)(nf + (size_t)n1 * IN_DIM);
        float4 u0 = __ldg(&r0[lane]);
        float4 u1 = __ldg(&r0[32 + lane]);
        float4 v0 = __ldg(&r1[lane]);
        float4 v1 = __ldg(&r1[32 + lane]);
        a0.x += u0.x; a0.y += u0.y; a0.z += u0.z; a0.w += u0.w;
        a1.x += u1.x; a1.y += u1.y; a1.z += u1.z; a1.w += u1.w;
        a0.x += v0.x; a0.y += v0.y; a0.z += v0.z; a0.w += v0.w;
        a1.x += v1.x; a1.y += v1.y; a1.z += v1.z; a1.w += v1.w;
    }
    if (i < end) {
        int n = g_csr[i];
        const float4* row = (const float4*)(nf + (size_t)n * IN_DIM);
        float4 v0 = __ldg(&row[lane]);
        float4 v1 = __ldg(&row[32 + lane]);
        a0.x += v0.x; a0.y += v0.y; a0.z += v0.z; a0.w += v0.w;
        a1.x += v1.x; a1.y += v1.y; a1.z += v1.z; a1.w += v1.w;
    }
    int cnt = end - beg;
    float inv = 1.f / (float)(cnt > 0 ? cnt : 1);
    a0.x *= inv; a0.y *= inv; a0.z *= inv; a0.w *= inv;
    a1.x *= inv; a1.y *= inv; a1.z *= inv; a1.w *= inv;
    float4* dst = (float4*)(g_edge_feat + (size_t)gw * IN_DIM);
    dst[lane]      = a0;
    dst[32 + lane] = a1;
}

// ---------------- K5: fused MLP with smem-staged double-buffered W1 ----------------
// 128 threads, ROWS=25 rows/block, 2000 blocks. Thread tid owns GEMM1 column tid.
// W1 staged in 8 tiles of 32 k-rows (16KB each, double buffered via cp.async).
#define ROWS 25
#define KTILE 32
#define NTILES (IN_DIM / KTILE)

// dynamic smem layout (floats):
//   Xs  [25][256]            : 6400
//   Hs  [25][128]            : 3200
//   W2s [128*17]             : 2176
//   b2s [32]  (pad)          : 32
//   W1s [2][KTILE][128]      : 8192
#define OFF_XS   0
#define OFF_HS   (OFF_XS + ROWS * IN_DIM)
#define OFF_W2S  (OFF_HS + ROWS * HIDDEN)
#define OFF_B2S  (OFF_W2S + HIDDEN * OUT_DIM)
#define OFF_W1S  (OFF_B2S + 32)
#define MLP_SMEM_FLOATS (OFF_W1S + 2 * KTILE * HIDDEN)

__global__ void __launch_bounds__(128) mlp_kernel(
    const float* __restrict__ W1, const float* __restrict__ b1,
    const float* __restrict__ lng, const float* __restrict__ lnb,
    const float* __restrict__ W2, const float* __restrict__ b2,
    float* __restrict__ out)
{
    extern __shared__ float sm[];
    float* Xs  = sm + OFF_XS;
    float* Hs  = sm + OFF_HS;
    float* W2s = sm + OFF_W2S;
    float* b2s = sm + OFF_B2S;
    float* W1s = sm + OFF_W1S;   // [2][KTILE][HIDDEN]

    int tid  = threadIdx.x;
    int row0 = blockIdx.x * ROWS;

    // prefetch W1 tile 0 (32 rows x 128 cols = 1024 float4; 8 per thread)
    {
        const float4* src = (const float4*)W1;
        float4* dst = (float4*)W1s;
        #pragma unroll
        for (int j = 0; j < 8; j++) {
            int idx = tid + j * 128;
            cp_async16(&dst[idx], &src[idx]);
        }
        cp_async_commit();
    }

    // load X tile, W2, b2
    for (int idx = tid; idx < ROWS * (IN_DIM / 4); idx += 128) {
        int r = idx / (IN_DIM / 4);
        int c = idx % (IN_DIM / 4);
        ((float4*)(Xs + r * IN_DIM))[c] =
            ((const float4*)(g_edge_feat + (size_t)(row0 + r) * IN_DIM))[c];
    }
    for (int idx = tid; idx < HIDDEN * OUT_DIM; idx += 128) W2s[idx] = W2[idx];
    if (tid < OUT_DIM) b2s[tid] = b2[tid];

    unsigned long long acc2[ROWS];
    #pragma unroll
    for (int r = 0; r < ROWS; r++) acc2[r] = 0ULL;

    #pragma unroll 1
    for (int t = 0; t < NTILES; t++) {
        // prefetch next tile into other buffer
        if (t + 1 < NTILES) {
            const float4* src = (const float4*)(W1 + (t + 1) * KTILE * HIDDEN);
            float4* dst = (float4*)(W1s + ((t + 1) & 1) * KTILE * HIDDEN);
            #pragma unroll
            for (int j = 0; j < 8; j++) {
                int idx = tid + j * 128;
                cp_async16(&dst[idx], &src[idx]);
            }
            cp_async_commit();
            cp_async_wait<1>();   // tile t has landed
        } else {
            cp_async_wait<0>();
        }
        __syncthreads();          // tile t visible to all; prev compute done before overwrite

        const float* Wt = W1s + (t & 1) * KTILE * HIDDEN;
        int kbase = t * KTILE;
        #pragma unroll
        for (int kk = 0; kk < KTILE; kk += 4) {
            float w0 = Wt[(kk + 0) * HIDDEN + tid];
            float w1 = Wt[(kk + 1) * HIDDEN + tid];
            float w2 = Wt[(kk + 2) * HIDDEN + tid];
            float w3 = Wt[(kk + 3) * HIDDEN + tid];
            unsigned long long wA = pack_f32x2(w0, w1);
            unsigned long long wB = pack_f32x2(w2, w3);
            #pragma unroll
            for (int r = 0; r < ROWS; r++) {
                ulonglong2 xx = *(const ulonglong2*)(Xs + r * IN_DIM + kbase + kk);
                fma_f32x2(acc2[r], xx.x, wA);
                fma_f32x2(acc2[r], xx.y, wB);
            }
        }
        __syncthreads();          // done reading buffer before next overwrite
    }

    float b1v = b1[tid];
    #pragma unroll
    for (int r = 0; r < ROWS; r++) {
        float2 p = unpack_f32x2(acc2[r]);
        Hs[r * HIDDEN + tid] = p.x + p.y + b1v;
    }
    __syncthreads();

    // LayerNorm + ReLU, warp-per-row
    int wid = tid >> 5, lane = tid & 31;
    for (int r = wid; r < ROWS; r += 4) {
        float s = 0.f, s2 = 0.f;
        #pragma unroll
        for (int j = 0; j < 4; j++) {
            float v = Hs[r * HIDDEN + lane + 32 * j];
            s += v; s2 += v * v;
        }
        #pragma unroll
        for (int o = 16; o; o >>= 1) {
            s  += __shfl_xor_sync(0xffffffffu, s, o);
            s2 += __shfl_xor_sync(0xffffffffu, s2, o);
        }
        float mu  = s * (1.f / HIDDEN);
        float var = s2 * (1.f / HIDDEN) - mu * mu;
        float rs  = rsqrtf(var + LN_EPS);
        #pragma unroll
        for (int j = 0; j < 4; j++) {
            int c = lane + 32 * j;
            float v = (Hs[r * HIDDEN + c] - mu) * rs * lng[c] + lnb[c];
            Hs[r * HIDDEN + c] = fmaxf(v, 0.f);
        }
    }
    __syncthreads();

    // GEMM2
    for (int idx = tid; idx < ROWS * OUT_DIM; idx += 128) {
        int r = idx / OUT_DIM, o = idx % OUT_DIM;
        float s = b2s[o];
        #pragma unroll 8
        for (int j = 0; j < HIDDEN; j++)
            s = fmaf(Hs[r * HIDDEN + j], W2s[j * OUT_DIM + o], s);
        out[(size_t)(row0 + r) * OUT_DIM + o] = s;
    }
}

// ---------------- launch ----------------
extern "C" void kernel_launch(void* const* d_in, const int* in_sizes, int n_in,
                              void* d_out, int out_size)
{
    const float* node_features = (const float*)d_in[0];
    const int*   he            = (const int*)d_in[1];   // int32 (JAX x64 disabled)
    const float* W1            = (const float*)d_in[2];
    const float* b1            = (const float*)d_in[3];
    const float* ln_g          = (const float*)d_in[4];
    const float* ln_b          = (const float*)d_in[5];
    const float* W2            = (const float*)d_in[6];
    const float* b2            = (const float*)d_in[7];
    float*       out           = (float*)d_out;

    static const int SCAN_SMEM = NUM_EDGES * (int)sizeof(int);       // 200000 B
    static const int MLP_SMEM  = MLP_SMEM_FLOATS * (int)sizeof(float); // ~80 KB
    static bool attr_done = false;
    if (!attr_done) {
        cudaFuncSetAttribute(scan_kernel, cudaFuncAttributeMaxDynamicSharedMemorySize, SCAN_SMEM);
        cudaFuncSetAttribute(mlp_kernel,  cudaFuncAttributeMaxDynamicSharedMemorySize, MLP_SMEM);
        attr_done = true;
    }

    zero_counts_kernel<<<(NUM_EDGES + 255) / 256, 256>>>();
    count_kernel<<<(NUM_CONN + 255) / 256, 256>>>(he);
    scan_kernel<<<1, 1024, SCAN_SMEM>>>();
    fill_kernel<<<(NUM_CONN + 255) / 256, 256>>>(he);
    aggregate_kernel<<<(NUM_EDGES * 32 + 255) / 256, 256>>>(node_features);
    mlp_kernel<<<NUM_EDGES / ROWS, 128, MLP_SMEM>>>(W1, b1, ln_g, ln_b, W2, b2, out);
}